// round 15
// baseline (speedup 1.0000x reference)
#include <cuda_runtime.h>

#define NN      262144          // 64^3
#define NNZ_TOT (7 * NN)
#define BS      128
#define CH      32              // batch chunk width
#define NCHUNK  (BS / CH)       // 4
#define TROWS   64              // n rows per block in init/reduce_prep
#define TGRID   (NN / TROWS)    // 4096

// Resident scratch: ypT + yhT = 64 MB, fits L2 with slack.
__device__ float  g_ypT[(size_t)NN * CH];   // y_pred chunk (N, 32)  32 MB
__device__ float  g_yhT[(size_t)NN * CH];   // Yhat  chunk (N, 32)  32 MB
__device__ double g_acc[5 * BS];            // s1..s5 per batch element

// ---- init (chunk 0): transpose yp (float4 tiles), zero yhT, zero acc
// grid = TGRID, block = 256
__global__ void __launch_bounds__(256) init_kernel(const float* __restrict__ yp) {
    __shared__ float smT[TROWS][33];
    int tid = threadIdx.x;
    int j   = tid >> 3;                 // 0..31 batch row
    int c0  = tid & 7;                  // float4 col
    const float4* ypr = (const float4*)(yp + (size_t)j * NN) + blockIdx.x * 16;
#pragma unroll
    for (int pass = 0; pass < 2; pass++) {
        int n4 = pass * 8 + c0;
        float4 v = __ldcs(&ypr[n4]);
        smT[n4 * 4 + 0][j] = v.x;
        smT[n4 * 4 + 1][j] = v.y;
        smT[n4 * 4 + 2][j] = v.z;
        smT[n4 * 4 + 3][j] = v.w;
    }
    // zero yhT rows of this block: 64 rows * 32 = 512 float4
    float4* yh4 = (float4*)g_yhT;
#pragma unroll
    for (int pass = 0; pass < 2; pass++)
        yh4[(size_t)blockIdx.x * 512 + pass * 256 + tid] = make_float4(0.f, 0.f, 0.f, 0.f);
    if (blockIdx.x == 0)
        for (int i = tid; i < 5 * BS; i += 256) g_acc[i] = 0.0;
    __syncthreads();
    int tx = tid & 31, ty = tid >> 5;   // 32 x 8
    size_t nbase = (size_t)blockIdx.x * TROWS;
#pragma unroll
    for (int r = 0; r < TROWS; r += 8)
        g_ypT[(nbase + ty + r) * 32 + tx] = smT[ty + r][tx];
}

// ---- per-chunk scatter: Yhat_c[:, r] += v * yp_c[:, c]   (L2-capped)
__global__ void scatter_chunk(const float* __restrict__ vals,
                              const int* __restrict__ rows,
                              const int* __restrict__ cols) {
    const float4* yp4 = (const float4*)g_ypT;
    float4*       yh4 = (float4*)g_yhT;
    int gid    = blockIdx.x * blockDim.x + threadIdx.x;
    int stride = gridDim.x * blockDim.x;
    int sub    = gid & 7;
    for (int q = gid >> 3; q < NNZ_TOT; q += (stride >> 3)) {
        int   r = __ldcs(rows + q);
        int   c = __ldcs(cols + q);
        float v = __ldcs(vals + q);
        float4 p = __ldg(&yp4[(size_t)c * 8 + sub]);
        atomicAdd(&yh4[(size_t)r * 8 + sub],
                  make_float4(v * p.x, v * p.y, v * p.z, v * p.w));
    }
}

// ---- fused reduce(c) + in-place prep(c+1), 64-row blocks, latency-hidden.
// Phase order per block:
//   A1: yt tile -> smem (DRAM)                          [sync]
//   B-issue: next chunk's yp float4 loads -> REGISTERS  (no consumer yet)
//   A2: compute s1..s5 (p/h from L2), zero yhT if needed
//   reduction tree + g_acc atomics                      [sync]
//   B-store: regs -> smem -> ypT (in-place, same rows)
// grid = TGRID, block = 256.
__global__ void __launch_bounds__(256) reduce_prep(const float* __restrict__ yt,
                                                   const float* __restrict__ yp,
                                                   int b0, int has_prep) {
    __shared__ float smT[TROWS][33];
    __shared__ float red[5][8][32];
    int tid  = threadIdx.x;
    int lane = tid & 31;
    int w    = tid >> 5;
    int j    = tid >> 3;                // 0..31 batch row (tile loads)
    int c0   = tid & 7;                 // float4 col (tile loads)

    // --- A1: yt tile (64 n x 32 b) transposed into smem.
    {
        const float4* ytr = (const float4*)(yt + (size_t)(b0 + j) * NN) + blockIdx.x * 16;
#pragma unroll
        for (int pass = 0; pass < 2; pass++) {
            int n4 = pass * 8 + c0;
            float4 v = __ldcs(&ytr[n4]);
            smT[n4 * 4 + 0][j] = v.x;
            smT[n4 * 4 + 1][j] = v.y;
            smT[n4 * 4 + 2][j] = v.z;
            smT[n4 * 4 + 3][j] = v.w;
        }
    }
    __syncthreads();

    // --- B-issue: next chunk's yp loads into registers (latency hides
    // under A2 compute; consumed only after the reduction).
    float4 bld0, bld1;
    if (has_prep) {
        const float4* ypr = (const float4*)(yp + (size_t)(b0 + CH + j) * NN) + blockIdx.x * 16;
        bld0 = __ldcs(&ypr[c0]);
        bld1 = __ldcs(&ypr[8 + c0]);
    }

    // --- A2: compute over this block's 64 rows (16 row-groups; warp w: 2).
    const float4* yp4 = (const float4*)g_ypT;
    float4*       yh4 = (float4*)g_yhT;
    int j0   = (lane & 7) * 4;
    int nsub = lane >> 3;

    float a1[4] = {0, 0, 0, 0}, a2[4] = {0, 0, 0, 0}, a3[4] = {0, 0, 0, 0};
    float a4[4] = {0, 0, 0, 0}, a5[4] = {0, 0, 0, 0};

#pragma unroll
    for (int k2 = 0; k2 < 2; k2++) {
        int rg_l = w * 2 + k2;                        // local row-group 0..15
        size_t f = ((size_t)blockIdx.x * 16 + rg_l) * 32 + lane;
        float4 p = __ldg(&yp4[f]);
        float4 h = yh4[f];
        if (has_prep)                                 // another scatter follows
            yh4[f] = make_float4(0.f, 0.f, 0.f, 0.f);
        int nl = rg_l * 4 + nsub;
        float t0 = smT[nl][j0 + 0];
        float t1 = smT[nl][j0 + 1];
        float t2 = smT[nl][j0 + 2];
        float t3 = smT[nl][j0 + 3];
        a1[0] += t0 * p.x; a1[1] += t1 * p.y; a1[2] += t2 * p.z; a1[3] += t3 * p.w;
        a2[0] += p.x * h.x; a2[1] += p.y * h.y; a2[2] += p.z * h.z; a2[3] += p.w * h.w;
        a3[0] += t0 * t0;  a3[1] += t1 * t1;  a3[2] += t2 * t2;  a3[3] += t3 * t3;
        a4[0] += t0 * h.x; a4[1] += t1 * h.y; a4[2] += t2 * h.z; a4[3] += t3 * h.w;
        a5[0] += h.x * h.x; a5[1] += h.y * h.y; a5[2] += h.z * h.z; a5[3] += h.w * h.w;
    }

    // lanes {l, l+8, l+16, l+24} hold the same 4 batch columns
#pragma unroll
    for (int k = 0; k < 4; k++) {
#pragma unroll
        for (int d = 16; d >= 8; d >>= 1) {
            a1[k] += __shfl_down_sync(0xffffffffu, a1[k], d);
            a2[k] += __shfl_down_sync(0xffffffffu, a2[k], d);
            a3[k] += __shfl_down_sync(0xffffffffu, a3[k], d);
            a4[k] += __shfl_down_sync(0xffffffffu, a4[k], d);
            a5[k] += __shfl_down_sync(0xffffffffu, a5[k], d);
        }
    }

    if (lane < 8) {
#pragma unroll
        for (int k = 0; k < 4; k++) {
            red[0][w][lane * 4 + k] = a1[k];
            red[1][w][lane * 4 + k] = a2[k];
            red[2][w][lane * 4 + k] = a3[k];
            red[3][w][lane * 4 + k] = a4[k];
            red[4][w][lane * 4 + k] = a5[k];
        }
    }
    __syncthreads();   // also: all smT reads done -> smT reusable below

    if (tid < 160) {
        int acc = tid >> 5;
        int jj  = tid & 31;
        float s = 0.f;
#pragma unroll
        for (int ww = 0; ww < 8; ww++) s += red[acc][ww][jj];
        atomicAdd(&g_acc[acc * BS + b0 + jj], (double)s);
    }

    // --- B-store: registers -> smem transpose -> ypT (in-place, hot lines)
    if (has_prep) {
        int n4a = c0, n4b = 8 + c0;
        smT[n4a * 4 + 0][j] = bld0.x;
        smT[n4a * 4 + 1][j] = bld0.y;
        smT[n4a * 4 + 2][j] = bld0.z;
        smT[n4a * 4 + 3][j] = bld0.w;
        smT[n4b * 4 + 0][j] = bld1.x;
        smT[n4b * 4 + 1][j] = bld1.y;
        smT[n4b * 4 + 2][j] = bld1.z;
        smT[n4b * 4 + 3][j] = bld1.w;
        __syncthreads();
        int tx = tid & 31, ty = tid >> 5;     // 32 x 8
        size_t nbase = (size_t)blockIdx.x * TROWS;
#pragma unroll
        for (int r = 0; r < TROWS; r += 8)
            g_ypT[(nbase + ty + r) * 32 + tx] = smT[ty + r][tx];
    }
}

// ------------------------------------------------------------ final scalar
__global__ void final_kernel(float* out) {
    int b = threadIdx.x;            // 128 threads
    double s1 = g_acc[0 * BS + b];
    double s2 = g_acc[1 * BS + b];
    double s3 = g_acc[2 * BS + b];
    double s4 = g_acc[3 * BS + b];
    double s5 = g_acc[4 * BS + b];
    double c  = s1 / s2;
    double r  = s3 - 2.0 * c * s4 + c * c * s5;
    __shared__ double sh[128];
    sh[b] = r;
    __syncthreads();
    for (int s = 64; s > 0; s >>= 1) {
        if (b < s) sh[b] += sh[b + s];
        __syncthreads();
    }
    if (b == 0) out[0] = (float)(sh[0] / (double)BS);
}

extern "C" void kernel_launch(void* const* d_in, const int* in_sizes, int n_in,
                              void* d_out, int out_size) {
    const float* yp   = (const float*)d_in[0];
    const float* yt   = (const float*)d_in[1];
    const float* vals = (const float*)d_in[2];
    const int*   rows = (const int*)d_in[3];
    const int*   cols = (const int*)d_in[4];
    float*       out  = (float*)d_out;

    init_kernel<<<TGRID, 256>>>(yp);
    for (int c = 0; c < NCHUNK; c++) {
        scatter_chunk<<<2368, 256>>>(vals, rows, cols);
        reduce_prep<<<TGRID, 256>>>(yt, yp, c * CH, c < NCHUNK - 1);
    }
    final_kernel<<<1, BS>>>(out);
}

// round 16
// speedup vs baseline: 1.2113x; 1.2113x over previous
#include <cuda_runtime.h>

#define NN      262144          // 64^3
#define NNZ_TOT (7 * NN)
#define BS      128
#define CH      32              // batch chunk width
#define NCHUNK  (BS / CH)       // 4
#define NSLOT   16              // spread accumulator copies (atomic contention)

// Resident scratch: ypT + yhT = 64 MB, fits L2 with slack.
__device__ float  g_ypT[(size_t)NN * CH];   // y_pred chunk (N, 32)  32 MB
__device__ float  g_yhT[(size_t)NN * CH];   // Yhat  chunk (N, 32)  32 MB
__device__ double g_acc[NSLOT][5 * BS];     // spread s1..s5 accumulators

// ---- init (chunk 0): transpose yp, zero yhT, zero acc
// grid = NN/32, block = (32, 8)
__global__ void init_kernel(const float* __restrict__ yp) {
    __shared__ float tp[32][33];
    int n0 = blockIdx.x * 32;
    int tx = threadIdx.x, ty = threadIdx.y;
    int tid = ty * 32 + tx;
#pragma unroll
    for (int r = 0; r < 32; r += 8)
        tp[ty + r][tx] = __ldcs(yp + (size_t)(ty + r) * NN + n0 + tx);
    ((float4*)g_yhT)[(size_t)n0 * 8 + tid] = make_float4(0.f, 0.f, 0.f, 0.f);
    if (blockIdx.x == 0)
        for (int i = tid; i < NSLOT * 5 * BS; i += 256)
            ((double*)g_acc)[i] = 0.0;
    __syncthreads();
#pragma unroll
    for (int r = 0; r < 32; r += 8)
        g_ypT[(size_t)(n0 + ty + r) * 32 + tx] = tp[tx][ty + r];
}

// ---- per-chunk scatter: Yhat_c[:, r] += v * yp_c[:, c]   (LTS-cap)
__global__ void scatter_chunk(const float* __restrict__ vals,
                              const int* __restrict__ rows,
                              const int* __restrict__ cols) {
    const float4* yp4 = (const float4*)g_ypT;
    float4*       yh4 = (float4*)g_yhT;
    int gid    = blockIdx.x * blockDim.x + threadIdx.x;
    int stride = gridDim.x * blockDim.x;
    int sub    = gid & 7;
    for (int q = gid >> 3; q < NNZ_TOT; q += (stride >> 3)) {
        int   r = __ldcs(rows + q);
        int   c = __ldcs(cols + q);
        float v = __ldcs(vals + q);
        float4 p = __ldg(&yp4[(size_t)c * 8 + sub]);
        atomicAdd(&yh4[(size_t)r * 8 + sub],
                  make_float4(v * p.x, v * p.y, v * p.z, v * p.w));
    }
}

// ---- fused reduce(c) + in-place prep(c+1)  (R14 structure, 128-row blocks)
// grid = NN/128 = 2048, block = 256 (8 warps).
__global__ void reduce_prep(const float* __restrict__ yt,
                            const float* __restrict__ yp,
                            int b0, int has_prep) {
    __shared__ float smT[128][33];
    __shared__ float red[5][8][32];
    int tid  = threadIdx.x;
    int lane = tid & 31;
    int w    = tid >> 5;

    // --- Phase A1: yt tile (128 n x 32 b), transposed into smem.
    {
        int j  = tid >> 3;
        int c0 = tid & 7;
        const float4* ytr = (const float4*)(yt + (size_t)(b0 + j) * NN) + blockIdx.x * 32;
#pragma unroll
        for (int pass = 0; pass < 4; pass++) {
            int n4 = pass * 8 + c0;
            float4 v = __ldcs(&ytr[n4]);
            smT[n4 * 4 + 0][j] = v.x;
            smT[n4 * 4 + 1][j] = v.y;
            smT[n4 * 4 + 2][j] = v.z;
            smT[n4 * 4 + 3][j] = v.w;
        }
    }
    __syncthreads();

    const float4* yp4 = (const float4*)g_ypT;
    float4*       yh4 = (float4*)g_yhT;

    int j0   = (lane & 7) * 4;
    int nsub = lane >> 3;

    float a1[4] = {0, 0, 0, 0}, a2[4] = {0, 0, 0, 0}, a3[4] = {0, 0, 0, 0};
    float a4[4] = {0, 0, 0, 0}, a5[4] = {0, 0, 0, 0};

    // --- Phase A2: compute over this block's 128 rows.
#pragma unroll
    for (int k2 = 0; k2 < 4; k2++) {
        int rg_l = w * 4 + k2;                       // local row-group 0..31
        size_t f = ((size_t)blockIdx.x * 32 + rg_l) * 32 + lane;
        float4 p = __ldg(&yp4[f]);
        float4 h = yh4[f];
        if (has_prep)                                // another scatter follows
            yh4[f] = make_float4(0.f, 0.f, 0.f, 0.f);
        int nl = rg_l * 4 + nsub;
        float t0 = smT[nl][j0 + 0];
        float t1 = smT[nl][j0 + 1];
        float t2 = smT[nl][j0 + 2];
        float t3 = smT[nl][j0 + 3];
        a1[0] += t0 * p.x; a1[1] += t1 * p.y; a1[2] += t2 * p.z; a1[3] += t3 * p.w;
        a2[0] += p.x * h.x; a2[1] += p.y * h.y; a2[2] += p.z * h.z; a2[3] += p.w * h.w;
        a3[0] += t0 * t0;  a3[1] += t1 * t1;  a3[2] += t2 * t2;  a3[3] += t3 * t3;
        a4[0] += t0 * h.x; a4[1] += t1 * h.y; a4[2] += t2 * h.z; a4[3] += t3 * h.w;
        a5[0] += h.x * h.x; a5[1] += h.y * h.y; a5[2] += h.z * h.z; a5[3] += h.w * h.w;
    }

    // lanes {l, l+8, l+16, l+24} hold the same 4 batch columns
#pragma unroll
    for (int k = 0; k < 4; k++) {
#pragma unroll
        for (int d = 16; d >= 8; d >>= 1) {
            a1[k] += __shfl_down_sync(0xffffffffu, a1[k], d);
            a2[k] += __shfl_down_sync(0xffffffffu, a2[k], d);
            a3[k] += __shfl_down_sync(0xffffffffu, a3[k], d);
            a4[k] += __shfl_down_sync(0xffffffffu, a4[k], d);
            a5[k] += __shfl_down_sync(0xffffffffu, a5[k], d);
        }
    }

    if (lane < 8) {
#pragma unroll
        for (int k = 0; k < 4; k++) {
            red[0][w][lane * 4 + k] = a1[k];
            red[1][w][lane * 4 + k] = a2[k];
            red[2][w][lane * 4 + k] = a3[k];
            red[3][w][lane * 4 + k] = a4[k];
            red[4][w][lane * 4 + k] = a5[k];
        }
    }
    __syncthreads();

    if (tid < 160) {
        int acc = tid >> 5;
        int j   = tid & 31;
        float s = 0.f;
#pragma unroll
        for (int ww = 0; ww < 8; ww++) s += red[acc][ww][j];
        // spread atomics: 16 slots -> per-address chain 2048 -> 128
        atomicAdd(&g_acc[blockIdx.x & (NSLOT - 1)][acc * BS + b0 + j], (double)s);
    }

    // --- Phase B: in-place prep of next chunk into this block's ypT rows.
    if (has_prep) {
        int b0n = b0 + CH;
        {
            int j  = tid >> 3;
            int c0 = tid & 7;
            const float4* ypr = (const float4*)(yp + (size_t)(b0n + j) * NN) + blockIdx.x * 32;
#pragma unroll
            for (int pass = 0; pass < 4; pass++) {
                int n4 = pass * 8 + c0;
                float4 v = __ldcs(&ypr[n4]);
                smT[n4 * 4 + 0][j] = v.x;
                smT[n4 * 4 + 1][j] = v.y;
                smT[n4 * 4 + 2][j] = v.z;
                smT[n4 * 4 + 3][j] = v.w;
            }
        }
        __syncthreads();
        int tx = tid & 31, ty = tid >> 5;     // 32 x 8
        size_t nbase = (size_t)blockIdx.x * 128;
#pragma unroll
        for (int r = 0; r < 128; r += 8)
            g_ypT[(nbase + ty + r) * 32 + tx] = smT[ty + r][tx];
    }
}

// ------------------------------------------------------------ final scalar
__global__ void final_kernel(float* out) {
    int b = threadIdx.x;            // 128 threads
    double s1 = 0, s2 = 0, s3 = 0, s4 = 0, s5 = 0;
#pragma unroll
    for (int sl = 0; sl < NSLOT; sl++) {
        s1 += g_acc[sl][0 * BS + b];
        s2 += g_acc[sl][1 * BS + b];
        s3 += g_acc[sl][2 * BS + b];
        s4 += g_acc[sl][3 * BS + b];
        s5 += g_acc[sl][4 * BS + b];
    }
    double c  = s1 / s2;
    double r  = s3 - 2.0 * c * s4 + c * c * s5;
    __shared__ double sh[128];
    sh[b] = r;
    __syncthreads();
    for (int s = 64; s > 0; s >>= 1) {
        if (b < s) sh[b] += sh[b + s];
        __syncthreads();
    }
    if (b == 0) out[0] = (float)(sh[0] / (double)BS);
}

extern "C" void kernel_launch(void* const* d_in, const int* in_sizes, int n_in,
                              void* d_out, int out_size) {
    const float* yp   = (const float*)d_in[0];
    const float* yt   = (const float*)d_in[1];
    const float* vals = (const float*)d_in[2];
    const int*   rows = (const int*)d_in[3];
    const int*   cols = (const int*)d_in[4];
    float*       out  = (float*)d_out;

    init_kernel<<<NN / 32, dim3(32, 8)>>>(yp);
    for (int c = 0; c < NCHUNK; c++) {
        scatter_chunk<<<2368, 256>>>(vals, rows, cols);
        reduce_prep<<<NN / 128, 256>>>(yt, yp, c * CH, c < NCHUNK - 1);
    }
    final_kernel<<<1, BS>>>(out);
}

// round 17
// speedup vs baseline: 1.2265x; 1.0126x over previous
#include <cuda_runtime.h>

#define NN      262144          // 64^3
#define NNZ_TOT (7 * NN)
#define BS      128
#define CH      32              // batch chunk width
#define NCHUNK  (BS / CH)       // 4
#define NSLOT   16              // spread accumulator copies (atomic contention)
#define RGRID   (NN / 128)      // 2048 reduce_prep blocks

// Resident scratch: ypT + yhT = 64 MB, fits L2 with slack.
__device__ float    g_ypT[(size_t)NN * CH];   // y_pred chunk (N, 32)  32 MB
__device__ float    g_yhT[(size_t)NN * CH];   // Yhat  chunk (N, 32)  32 MB
__device__ double   g_acc[NSLOT][5 * BS];     // spread s1..s5 accumulators
__device__ unsigned g_ticket;                 // last-block ticket

// ---- init (chunk 0): transpose yp, zero yhT, zero acc + ticket
// grid = NN/32, block = (32, 8)
__global__ void init_kernel(const float* __restrict__ yp) {
    __shared__ float tp[32][33];
    int n0 = blockIdx.x * 32;
    int tx = threadIdx.x, ty = threadIdx.y;
    int tid = ty * 32 + tx;
#pragma unroll
    for (int r = 0; r < 32; r += 8)
        tp[ty + r][tx] = __ldcs(yp + (size_t)(ty + r) * NN + n0 + tx);
    ((float4*)g_yhT)[(size_t)n0 * 8 + tid] = make_float4(0.f, 0.f, 0.f, 0.f);
    if (blockIdx.x == 0) {
        for (int i = tid; i < NSLOT * 5 * BS; i += 256)
            ((double*)g_acc)[i] = 0.0;
        if (tid == 0) g_ticket = 0u;
    }
    __syncthreads();
#pragma unroll
    for (int r = 0; r < 32; r += 8)
        g_ypT[(size_t)(n0 + ty + r) * 32 + tx] = tp[tx][ty + r];
}

// ---- per-chunk scatter: Yhat_c[:, r] += v * yp_c[:, c]   (LTS-cap)
// grid = 1184 = exactly one wave (8 blocks/SM on 148 SMs)
__global__ void scatter_chunk(const float* __restrict__ vals,
                              const int* __restrict__ rows,
                              const int* __restrict__ cols) {
    const float4* yp4 = (const float4*)g_ypT;
    float4*       yh4 = (float4*)g_yhT;
    int gid    = blockIdx.x * blockDim.x + threadIdx.x;
    int stride = gridDim.x * blockDim.x;
    int sub    = gid & 7;
#pragma unroll 2
    for (int q = gid >> 3; q < NNZ_TOT; q += (stride >> 3)) {
        int   r = __ldcs(rows + q);
        int   c = __ldcs(cols + q);
        float v = __ldcs(vals + q);
        float4 p = __ldg(&yp4[(size_t)c * 8 + sub]);
        atomicAdd(&yh4[(size_t)r * 8 + sub],
                  make_float4(v * p.x, v * p.y, v * p.z, v * p.w));
    }
}

// ---- fused reduce(c) + in-place prep(c+1); on the last chunk the final
// scalar is computed by the last-finishing block (ticket pattern).
// grid = RGRID = 2048, block = 256 (8 warps).
__global__ void reduce_prep(const float* __restrict__ yt,
                            const float* __restrict__ yp,
                            float* __restrict__ out,
                            int b0, int has_prep) {
    __shared__ float smT[128][33];
    __shared__ float red[5][8][32];
    int tid  = threadIdx.x;
    int lane = tid & 31;
    int w    = tid >> 5;

    // --- Phase A1: yt tile (128 n x 32 b), transposed into smem.
    {
        int j  = tid >> 3;
        int c0 = tid & 7;
        const float4* ytr = (const float4*)(yt + (size_t)(b0 + j) * NN) + blockIdx.x * 32;
#pragma unroll
        for (int pass = 0; pass < 4; pass++) {
            int n4 = pass * 8 + c0;
            float4 v = __ldcs(&ytr[n4]);
            smT[n4 * 4 + 0][j] = v.x;
            smT[n4 * 4 + 1][j] = v.y;
            smT[n4 * 4 + 2][j] = v.z;
            smT[n4 * 4 + 3][j] = v.w;
        }
    }
    __syncthreads();

    const float4* yp4 = (const float4*)g_ypT;
    float4*       yh4 = (float4*)g_yhT;

    int j0   = (lane & 7) * 4;
    int nsub = lane >> 3;

    float a1[4] = {0, 0, 0, 0}, a2[4] = {0, 0, 0, 0}, a3[4] = {0, 0, 0, 0};
    float a4[4] = {0, 0, 0, 0}, a5[4] = {0, 0, 0, 0};

    // --- Phase A2: compute over this block's 128 rows.
#pragma unroll
    for (int k2 = 0; k2 < 4; k2++) {
        int rg_l = w * 4 + k2;                       // local row-group 0..31
        size_t f = ((size_t)blockIdx.x * 32 + rg_l) * 32 + lane;
        float4 p = __ldg(&yp4[f]);
        float4 h = yh4[f];
        if (has_prep)                                // another scatter follows
            yh4[f] = make_float4(0.f, 0.f, 0.f, 0.f);
        int nl = rg_l * 4 + nsub;
        float t0 = smT[nl][j0 + 0];
        float t1 = smT[nl][j0 + 1];
        float t2 = smT[nl][j0 + 2];
        float t3 = smT[nl][j0 + 3];
        a1[0] += t0 * p.x; a1[1] += t1 * p.y; a1[2] += t2 * p.z; a1[3] += t3 * p.w;
        a2[0] += p.x * h.x; a2[1] += p.y * h.y; a2[2] += p.z * h.z; a2[3] += p.w * h.w;
        a3[0] += t0 * t0;  a3[1] += t1 * t1;  a3[2] += t2 * t2;  a3[3] += t3 * t3;
        a4[0] += t0 * h.x; a4[1] += t1 * h.y; a4[2] += t2 * h.z; a4[3] += t3 * h.w;
        a5[0] += h.x * h.x; a5[1] += h.y * h.y; a5[2] += h.z * h.z; a5[3] += h.w * h.w;
    }

    // lanes {l, l+8, l+16, l+24} hold the same 4 batch columns
#pragma unroll
    for (int k = 0; k < 4; k++) {
#pragma unroll
        for (int d = 16; d >= 8; d >>= 1) {
            a1[k] += __shfl_down_sync(0xffffffffu, a1[k], d);
            a2[k] += __shfl_down_sync(0xffffffffu, a2[k], d);
            a3[k] += __shfl_down_sync(0xffffffffu, a3[k], d);
            a4[k] += __shfl_down_sync(0xffffffffu, a4[k], d);
            a5[k] += __shfl_down_sync(0xffffffffu, a5[k], d);
        }
    }

    if (lane < 8) {
#pragma unroll
        for (int k = 0; k < 4; k++) {
            red[0][w][lane * 4 + k] = a1[k];
            red[1][w][lane * 4 + k] = a2[k];
            red[2][w][lane * 4 + k] = a3[k];
            red[3][w][lane * 4 + k] = a4[k];
            red[4][w][lane * 4 + k] = a5[k];
        }
    }
    __syncthreads();

    if (tid < 160) {
        int acc = tid >> 5;
        int j   = tid & 31;
        float s = 0.f;
#pragma unroll
        for (int ww = 0; ww < 8; ww++) s += red[acc][ww][j];
        atomicAdd(&g_acc[blockIdx.x & (NSLOT - 1)][acc * BS + b0 + j], (double)s);
    }

    if (has_prep) {
        // --- Phase B: in-place prep of next chunk into this block's ypT rows.
        int b0n = b0 + CH;
        {
            int j  = tid >> 3;
            int c0 = tid & 7;
            const float4* ypr = (const float4*)(yp + (size_t)(b0n + j) * NN) + blockIdx.x * 32;
#pragma unroll
            for (int pass = 0; pass < 4; pass++) {
                int n4 = pass * 8 + c0;
                float4 v = __ldcs(&ypr[n4]);
                smT[n4 * 4 + 0][j] = v.x;
                smT[n4 * 4 + 1][j] = v.y;
                smT[n4 * 4 + 2][j] = v.z;
                smT[n4 * 4 + 3][j] = v.w;
            }
        }
        __syncthreads();
        int tx = tid & 31, ty = tid >> 5;     // 32 x 8
        size_t nbase = (size_t)blockIdx.x * 128;
#pragma unroll
        for (int r = 0; r < 128; r += 8)
            g_ypT[(nbase + ty + r) * 32 + tx] = smT[ty + r][tx];
    } else {
        // --- Last chunk: last-finishing block computes the final scalar.
        __shared__ double shf[128];
        __shared__ unsigned amLast;
        __threadfence();                      // make this block's adds visible
        __syncthreads();
        if (tid == 0)
            amLast = (atomicAdd(&g_ticket, 1u) == (unsigned)(gridDim.x - 1));
        __syncthreads();
        if (amLast) {
            if (tid < 128) {
                int b = tid;
                double s1 = 0, s2 = 0, s3 = 0, s4 = 0, s5 = 0;
#pragma unroll
                for (int sl = 0; sl < NSLOT; sl++) {
                    s1 += __ldcg(&g_acc[sl][0 * BS + b]);
                    s2 += __ldcg(&g_acc[sl][1 * BS + b]);
                    s3 += __ldcg(&g_acc[sl][2 * BS + b]);
                    s4 += __ldcg(&g_acc[sl][3 * BS + b]);
                    s5 += __ldcg(&g_acc[sl][4 * BS + b]);
                }
                double c = s1 / s2;
                shf[b] = s3 - 2.0 * c * s4 + c * c * s5;
            }
            __syncthreads();
            if (tid < 128) {
                for (int s = 64; s > 0; s >>= 1) {
                    if (tid < s) shf[tid] += shf[tid + s];
                    __syncthreads();
                }
                if (tid == 0) out[0] = (float)(shf[0] / (double)BS);
            }
        }
    }
}

extern "C" void kernel_launch(void* const* d_in, const int* in_sizes, int n_in,
                              void* d_out, int out_size) {
    const float* yp   = (const float*)d_in[0];
    const float* yt   = (const float*)d_in[1];
    const float* vals = (const float*)d_in[2];
    const int*   rows = (const int*)d_in[3];
    const int*   cols = (const int*)d_in[4];
    float*       out  = (float*)d_out;

    init_kernel<<<NN / 32, dim3(32, 8)>>>(yp);
    for (int c = 0; c < NCHUNK; c++) {
        scatter_chunk<<<1184, 256>>>(vals, rows, cols);
        reduce_prep<<<RGRID, 256>>>(yt, yp, out, c * CH, c < NCHUNK - 1);
    }
}